// round 8
// baseline (speedup 1.0000x reference)
#include <cuda_runtime.h>
#include <cuda_bf16.h>
#include <cstdint>

// Problem constants
#define BB 8
#define SS 4096           // WIDTH*WIDTH
#define EE 128
#define WIDTH 64
#define NEDGE 512         // 32 paths * 16 edges per batch

// Precomputed combined weights: Wc = Wv @ Wp, bc = bv @ Wp
__device__ float g_Wc[EE * EE];
__device__ float g_bc[EE];

// ---------------------------------------------------------------------------
// combine: Wc[i][j] = sum_k Wv[i][k] * Wp[k][j];  bc[j] = sum_k bv[k]*Wp[k][j]
// grid = EE blocks (one per row i), block = EE threads (one per col j)
__global__ void combine_kernel(const float* __restrict__ Wv,
                               const float* __restrict__ Wp,
                               const float* __restrict__ bv) {
    __shared__ float wvrow[EE];
    int i = blockIdx.x, j = threadIdx.x;
    wvrow[j] = Wv[i * EE + j];
    __syncthreads();
    float acc = 0.0f;
    #pragma unroll 16
    for (int k = 0; k < EE; k++)
        acc = fmaf(wvrow[k], Wp[k * EE + j], acc);
    g_Wc[i * EE + j] = acc;
    if (i == 0) {
        float b = 0.0f;
        #pragma unroll 16
        for (int k = 0; k < EE; k++)
            b = fmaf(bv[k], Wp[k * EE + j], b);
        g_bc[j] = b;
    }
}

// ---------------------------------------------------------------------------
// Fill attn region with bp broadcast: out[row*128 + e] = bp[e]
__global__ void fill_bp_kernel(float4* __restrict__ out, const float4* __restrict__ bp4) {
    unsigned tid = blockIdx.x * blockDim.x + threadIdx.x;   // 0 .. B*S*32-1
    out[tid] = bp4[tid & 31];
}

// ---------------------------------------------------------------------------
// Scatter adjacency ones into both A copies (after the big memset).
__global__ void set_edges_kernel(float* __restrict__ A1, float* __restrict__ A2,
                                 const int* __restrict__ edges) {
    int b = blockIdx.x;
    int i = threadIdx.x;           // 0..511
    const int4 v = ((const int4*)edges)[(size_t)b * NEDGE + i];
    int src = v.y * WIDTH + v.x;
    int dst = v.w * WIDTH + v.z;
    size_t off = ((size_t)b * SS + src) * SS + dst;
    A1[off] = 1.0f;
    A2[off] = 1.0f;
}

// ---------------------------------------------------------------------------
// Fused: for each FIRST-occurrence src edge i:
//   attn[b,src,:] = (sum over unique dsts of values[b,dst,:]) @ Wc + m*bc + bp
// grid = (NEDGE, BB), block = EE threads.
__global__ void fused_out_kernel(float* __restrict__ attn,
                                 const float* __restrict__ values,
                                 const float* __restrict__ bp,
                                 const int* __restrict__ edges) {
    __shared__ int src_s[NEDGE];
    __shared__ int dst_s[NEDGE];
    __shared__ unsigned char firstpair[NEDGE];
    __shared__ float accv[EE];
    __shared__ int sdup;

    int b = blockIdx.y;
    int i = blockIdx.x;
    int e = threadIdx.x;

    const int4* eg = (const int4*)(edges + (size_t)b * NEDGE * 4);
    for (int t = e; t < NEDGE; t += EE) {
        int4 v = eg[t];
        src_s[t] = v.y * WIDTH + v.x;
        dst_s[t] = v.w * WIDTH + v.z;
    }
    if (e == 0) sdup = 0;
    __syncthreads();

    int my_src = src_s[i];

    // first-occurrence-of-src check (cooperative scan over j < i)
    bool d = false;
    for (int j = e; j < i; j += EE)
        if (src_s[j] == my_src) { d = true; break; }
    if (d) sdup = 1;
    __syncthreads();
    if (sdup) return;

    // firstpair flags: edge j (with src==my_src) counts iff no earlier edge
    // has the same (src,dst) pair
    for (int j = e; j < NEDGE; j += EE) {
        unsigned char f = 0;
        if (src_s[j] == my_src) {
            f = 1;
            int dj = dst_s[j];
            for (int k = 0; k < j; k++)
                if (src_s[k] == my_src && dst_s[k] == dj) { f = 0; break; }
        }
        firstpair[j] = f;
    }
    __syncthreads();

    // sum raw values rows over qualifying edges; count m
    float acc = 0.0f;
    int m = 0;
    for (int j = 0; j < NEDGE; j++) {
        if (firstpair[j]) {
            acc += values[((size_t)b * SS + dst_s[j]) * EE + e];
            m++;
        }
    }
    accv[e] = acc;
    __syncthreads();

    // one matvec against combined weight
    float o = fmaf((float)m, g_bc[e], bp[e]);
    #pragma unroll 16
    for (int k = 0; k < EE; k++)
        o = fmaf(accv[k], g_Wc[k * EE + e], o);

    attn[((size_t)b * SS + my_src) * EE + e] = o;
}

// ---------------------------------------------------------------------------
extern "C" void kernel_launch(void* const* d_in, const int* in_sizes, int n_in,
                              void* d_out, int out_size) {
    (void)in_sizes; (void)n_in; (void)out_size;

    const float* values = (const float*)d_in[2];
    const int*   edges  = (const int*)  d_in[3];
    const float* Wv     = (const float*)d_in[8];
    const float* bv     = (const float*)d_in[9];
    const float* Wp     = (const float*)d_in[10];
    const float* bp     = (const float*)d_in[11];

    float* out  = (float*)d_out;
    float* attn = out;                                    // [B,S,E]
    float* A1   = out + (size_t)BB * SS * EE;             // [B,S,S]
    float* A2   = A1 + (size_t)BB * SS * SS;              // [B,S,S]

    // One-time resources (created on the eager correctness call, before capture)
    static cudaStream_t s1 = nullptr, s2 = nullptr;
    static cudaEvent_t ev_fork = nullptr, ev_j1 = nullptr, ev_j2 = nullptr;
    if (!s1) {
        cudaStreamCreateWithFlags(&s1, cudaStreamNonBlocking);
        cudaStreamCreateWithFlags(&s2, cudaStreamNonBlocking);
        cudaEventCreateWithFlags(&ev_fork, cudaEventDisableTiming);
        cudaEventCreateWithFlags(&ev_j1, cudaEventDisableTiming);
        cudaEventCreateWithFlags(&ev_j2, cudaEventDisableTiming);
    }

    // Fork both worker streams off the capture stream.
    cudaEventRecord(ev_fork, 0);
    cudaStreamWaitEvent(s1, ev_fork, 0);
    cudaStreamWaitEvent(s2, ev_fork, 0);

    // ---- branch s1: big adjacency zero (1.073 GB) then scatter ones ----
    cudaMemsetAsync(A1, 0, 2ull * BB * SS * SS * sizeof(float), s1);
    set_edges_kernel<<<BB, NEDGE, 0, s1>>>(A1, A2, edges);

    // ---- branch s2: combined-weight precompute + bp fill + fused output ----
    combine_kernel<<<EE, EE, 0, s2>>>(Wv, Wp, bv);
    {
        unsigned total4 = BB * SS * (EE / 4);             // 1,048,576 float4s
        fill_bp_kernel<<<total4 / 256, 256, 0, s2>>>((float4*)attn, (const float4*)bp);
    }
    {
        dim3 grid(NEDGE, BB);
        fused_out_kernel<<<grid, EE, 0, s2>>>(attn, values, bp, edges);
    }

    // Join both branches back to the capture stream.
    cudaEventRecord(ev_j1, s1);
    cudaEventRecord(ev_j2, s2);
    cudaStreamWaitEvent(0, ev_j1, 0);
    cudaStreamWaitEvent(0, ev_j2, 0);
}

// round 9
// speedup vs baseline: 1.6109x; 1.6109x over previous
#include <cuda_runtime.h>
#include <cuda_bf16.h>
#include <cstdint>

#define BB 8
#define SS 4096           // WIDTH*WIDTH
#define EE 128
#define WIDTH 64
#define NEDGE 512         // 32 paths * 16 edges per batch

// Scratch (static device allocations)
__device__ float g_Wc[EE * EE];          // Wv @ Wp
__device__ float g_bc[EE];               // bv @ Wp
__device__ int   g_src[BB][NEDGE];
__device__ int   g_dst[BB][NEDGE];
__device__ unsigned char g_fp[BB][NEDGE];   // first (src,dst) pair occurrence
__device__ unsigned char g_fs[BB][NEDGE];   // first src occurrence
__device__ unsigned char g_rowflag[BB * SS]; // row has >=1 edge (matvec writes it)

// ---------------------------------------------------------------------------
// prep: blocks 0..7 -> per-batch edge dedup + rowflags
//       blocks 8..39 -> Wc rows (4 rows per block), block 8 also bc
__global__ __launch_bounds__(512)
void prep_kernel(const int* __restrict__ edges,
                 const float* __restrict__ Wv,
                 const float* __restrict__ Wp,
                 const float* __restrict__ bv) {
    int t = threadIdx.x;
    if (blockIdx.x < BB) {
        int b = blockIdx.x;
        __shared__ int ssrc[NEDGE], sdst[NEDGE];
        int4 v = ((const int4*)edges)[(size_t)b * NEDGE + t];
        ssrc[t] = v.y * WIDTH + v.x;
        sdst[t] = v.w * WIDTH + v.z;
        // zero rowflags for this batch (8 per thread)
        #pragma unroll
        for (int r = 0; r < 8; r++) g_rowflag[b * SS + r * 512 + t] = 0;
        __syncthreads();

        int s = ssrc[t], d = sdst[t];
        unsigned char fp = 1, fs = 1;
        for (int j = 0; j < t; j++) {
            if (ssrc[j] == s) {
                fs = 0;
                if (sdst[j] == d) fp = 0;
            }
        }
        g_src[b][t] = s;
        g_dst[b][t] = d;
        g_fp[b][t] = fp;
        g_fs[b][t] = fs;
        if (fs) g_rowflag[b * SS + s] = 1;
    } else {
        int bi = blockIdx.x - BB;          // 0..31
        int r = bi * 4 + (t >> 7);         // Wc row
        int j = t & 127;                   // Wc col
        float acc = 0.0f;
        #pragma unroll 16
        for (int k = 0; k < EE; k++)
            acc = fmaf(Wv[r * EE + k], Wp[k * EE + j], acc);
        g_Wc[r * EE + j] = acc;
        if (bi == 0 && t < EE) {
            float bcx = 0.0f;
            #pragma unroll 16
            for (int k = 0; k < EE; k++)
                bcx = fmaf(bv[k], Wp[k * EE + j], bcx);
            g_bc[j] = bcx;
        }
    }
}

// ---------------------------------------------------------------------------
// mega: 16384 blocks x 128 threads.
//  phase 1 (blocks < 4096): fused matvec for edge (b>>9 batch, b&511 edge)
//  phase 2: bp-fill 2 attn rows (skip rowflag rows)
//  phase 3: stream-zero 4096 float4s of the A region
__global__ __launch_bounds__(128)
void mega_kernel(float* __restrict__ attn,       // [B,S,E]
                 float4* __restrict__ Az,        // A region as float4 (both copies)
                 const float* __restrict__ values,
                 const float4* __restrict__ bp4,
                 const float* __restrict__ bp) {
    int b = blockIdx.x;
    int tid = threadIdx.x;

    __shared__ int ssrc[NEDGE], sdst[NEDGE];
    __shared__ unsigned char sfp[NEDGE];
    __shared__ float accv[EE];

    // ---- phase 1: sparse fused matvec ----
    if (b < 4096) {
        int bb = b >> 9;
        int i = b & 511;
        if (g_fs[bb][i]) {
            for (int t2 = tid; t2 < NEDGE; t2 += 128) {
                ssrc[t2] = g_src[bb][t2];
                sdst[t2] = g_dst[bb][t2];
                sfp[t2]  = g_fp[bb][t2];
            }
            __syncthreads();
            int my = ssrc[i];
            int e = tid;
            float acc = 0.0f;
            int m = 0;
            for (int j = 0; j < NEDGE; j++) {
                if (sfp[j] && ssrc[j] == my) {
                    acc += values[(((size_t)bb << 12) + sdst[j]) * EE + e];
                    m++;
                }
            }
            accv[e] = acc;
            __syncthreads();
            float o = fmaf((float)m, g_bc[e], bp[e]);
            #pragma unroll 16
            for (int k = 0; k < EE; k++)
                o = fmaf(accv[k], g_Wc[k * EE + e], o);
            attn[(((size_t)bb << 12) + my) * EE + e] = o;
        }
    }

    // ---- phase 2: bp-fill rows 2b, 2b+1 (rows without edges) ----
    {
        float4 bpv = (tid < 32) ? bp4[tid] : make_float4(0.f, 0.f, 0.f, 0.f);
        #pragma unroll
        for (int rr = 0; rr < 2; rr++) {
            int row = 2 * b + rr;          // 0..32767
            if (!g_rowflag[row] && tid < 32) {
                ((float4*)attn)[(size_t)row * 32 + tid] = bpv;
            }
        }
    }

    // ---- phase 3: streaming zero of 64KB chunk of A ----
    {
        float4 z = make_float4(0.f, 0.f, 0.f, 0.f);
        float4* dst = Az + (size_t)b * 4096;
        #pragma unroll 8
        for (int t2 = tid; t2 < 4096; t2 += 128) {
            __stcs(dst + t2, z);
        }
    }
}

// ---------------------------------------------------------------------------
// Scatter adjacency ones into both A copies (after zeros).
__global__ void set_edges_kernel(float* __restrict__ A1, float* __restrict__ A2,
                                 const int* __restrict__ edges) {
    int b = blockIdx.x;
    int i = threadIdx.x;
    const int4 v = ((const int4*)edges)[(size_t)b * NEDGE + i];
    int src = v.y * WIDTH + v.x;
    int dst = v.w * WIDTH + v.z;
    size_t off = ((size_t)b * SS + src) * SS + dst;
    A1[off] = 1.0f;
    A2[off] = 1.0f;
}

// ---------------------------------------------------------------------------
extern "C" void kernel_launch(void* const* d_in, const int* in_sizes, int n_in,
                              void* d_out, int out_size) {
    (void)in_sizes; (void)n_in; (void)out_size;

    const float* values = (const float*)d_in[2];
    const int*   edges  = (const int*)  d_in[3];
    const float* Wv     = (const float*)d_in[8];
    const float* bv     = (const float*)d_in[9];
    const float* Wp     = (const float*)d_in[10];
    const float* bp     = (const float*)d_in[11];

    float* out  = (float*)d_out;
    float* attn = out;                                    // [B,S,E]
    float* A1   = out + (size_t)BB * SS * EE;             // [B,S,S]
    float* A2   = A1 + (size_t)BB * SS * SS;              // [B,S,S]

    // 1) dedup + combined weights
    prep_kernel<<<BB + 32, 512>>>(edges, Wv, Wp, bv);

    // 2) fused zero-fill + bp-fill + sparse matvec
    mega_kernel<<<16384, 128>>>(attn, (float4*)A1, values,
                                (const float4*)bp, bp);

    // 3) adjacency ones
    set_edges_kernel<<<BB, NEDGE>>>(A1, A2, edges);
}